// round 14
// baseline (speedup 1.0000x reference)
#include <cuda_runtime.h>
#include <cuda_bf16.h>
#include <float.h>
#include <stdint.h>

#define BSZ 16
#define NP  4096
#define ND  256
#define NC  512
#define MARGIN 1e-3f

#define NMT  32                 // m-tiles per batch == warp size (by design)
#define MAXC 4
#define LDT  72                 // B smem pitch in bf16 elems (64 + 8 pad)
#define LDA  72                 // A smem pitch in fp32 elems (64 + 8 pad)

// ---- scratch (static device memory) ----
__device__ __nv_bfloat16 g_kbf[NC * ND];                  // 256 KB
__device__ float g_smax[BSZ * NMT * NC];
__device__ int   g_scnt[BSZ * NMT * NC];
__device__ float g_cval[(size_t)BSZ * NMT * NC * MAXC];
__device__ int   g_cpos[(size_t)BSZ * NMT * NC * MAXC];
__device__ int   g_sync[BSZ * 4];                         // zero-init; reset in-kernel

// ---------------------------------------------------------------------------
// Micro-prep: kernels fp32 -> bf16 only (x stays fp32; converted in-gemm).
// ---------------------------------------------------------------------------
__global__ void prep_kernel(const float* __restrict__ kern) {
    int i = blockIdx.x * blockDim.x + threadIdx.x;   // 32768 float4
    float4 v = ((const float4*)kern)[i];
    ((__nv_bfloat162*)g_kbf)[i * 2]     = __floats2bfloat162_rn(v.x, v.y);
    ((__nv_bfloat162*)g_kbf)[i * 2 + 1] = __floats2bfloat162_rn(v.z, v.w);
}

__device__ __forceinline__ uint32_t packbf(float lo, float hi) {
    __nv_bfloat162 h = __floats2bfloat162_rn(lo, hi);
    return *(uint32_t*)&h;
}

// ---------------------------------------------------------------------------
// bf16 tensor GEMM 128x128 tile; A staged fp32 + converted at LDS time;
// fused argmax epilogue + embedded zeroing + LAST-BLOCK merge & scatter.
// ---------------------------------------------------------------------------
__global__ __launch_bounds__(256)
void gemm_kernel(const float* __restrict__ x, const float* __restrict__ kern,
                 float* __restrict__ outf) {
    extern __shared__ char smraw[];
    float*         Asf = (float*)smraw;                               // [2][128*LDA]
    __nv_bfloat16* Bs  = (__nv_bfloat16*)(smraw + 2 * 128 * LDA * 4); // [2][128*LDT]

    float4* out = (float4*)outf;
    const int b = blockIdx.z, mt = blockIdx.y, nt = blockIdx.x;
    const int tid = threadIdx.x, lane = tid & 31, warp = tid >> 5;
    const int wm = warp & 1, wn = warp >> 1;

    const float*         Ag = x + ((size_t)b * NP + mt * 128) * ND;
    const __nv_bfloat16* Bg = g_kbf + (size_t)nt * 128 * ND;

    float acc[4][4][4];
    #pragma unroll
    for (int i = 0; i < 4; ++i)
        #pragma unroll
        for (int j = 0; j < 4; ++j)
            #pragma unroll
            for (int q = 0; q < 4; ++q) acc[i][j][q] = 0.f;

    auto issue = [&](int kc, int st) {
        #pragma unroll
        for (int it = 0; it < 8; ++it) {              // A: 2048 x 16B fp32
            int i = it * 256 + tid;
            int r = i >> 4, c = (i & 15) * 4;
            uint32_t sa = (uint32_t)__cvta_generic_to_shared(
                &Asf[st * 128 * LDA + r * LDA + c]);
            const float* ga = Ag + (size_t)r * ND + kc * 64 + c;
            asm volatile("cp.async.cg.shared.global [%0], [%1], 16;" :: "r"(sa), "l"(ga) : "memory");
        }
        #pragma unroll
        for (int it = 0; it < 4; ++it) {              // B: 1024 x 16B bf16
            int i = it * 256 + tid;
            int r = i >> 3, c = (i & 7) * 8;
            uint32_t sb = (uint32_t)__cvta_generic_to_shared(
                &Bs[st * 128 * LDT + r * LDT + c]);
            const __nv_bfloat16* gb = Bg + (size_t)r * ND + kc * 64 + c;
            asm volatile("cp.async.cg.shared.global [%0], [%1], 16;" :: "r"(sb), "l"(gb) : "memory");
        }
        asm volatile("cp.async.commit_group;" ::: "memory");
    };

    issue(0, 0);
    issue(1, 1);

    // ---- embedded zeroing: this block's 2048-float4 slice of out ----
    {
        const int bid = (b * NMT + mt) * 4 + nt;
        float4* oz = out + (size_t)bid * 2048;
        const float4 z = make_float4(0.f, 0.f, 0.f, 0.f);
        #pragma unroll
        for (int it = 0; it < 8; ++it)
            oz[it * 256 + tid] = z;
    }

    const int lm = lane & 15, lk = (lane >> 4) * 8;
    const int gq = lane >> 2, k2 = (lane & 3) * 2;

    #pragma unroll
    for (int kc = 0; kc < 4; ++kc) {
        if (kc < 3) asm volatile("cp.async.wait_group 1;" ::: "memory");
        else        asm volatile("cp.async.wait_group 0;" ::: "memory");
        __syncthreads();

        int st = kc & 1;
        const float*         Ab = Asf + st * 128 * LDA + (wm * 64) * LDA;
        const __nv_bfloat16* Bb = Bs  + st * 128 * LDT + (wn * 32) * LDT;

        #pragma unroll
        for (int ks = 0; ks < 4; ++ks) {
            const int kb = ks * 16 + k2;
            uint32_t af[4][4], bfv[2][4];
            #pragma unroll
            for (int i = 0; i < 4; ++i) {
                const float* ra = Ab + (i * 16 + gq) * LDA;
                float2 p0 = *(const float2*)(ra + kb);
                float2 p1 = *(const float2*)(ra + 8 * LDA + kb);
                float2 p2 = *(const float2*)(ra + kb + 8);
                float2 p3 = *(const float2*)(ra + 8 * LDA + kb + 8);
                af[i][0] = packbf(p0.x, p0.y);
                af[i][1] = packbf(p1.x, p1.y);
                af[i][2] = packbf(p2.x, p2.y);
                af[i][3] = packbf(p3.x, p3.y);
            }
            #pragma unroll
            for (int j = 0; j < 2; ++j) {
                uint32_t addr = (uint32_t)__cvta_generic_to_shared(
                    Bb + (j * 16 + lm) * LDT + ks * 16 + lk);
                asm volatile("ldmatrix.sync.aligned.m8n8.x4.shared.b16 {%0,%1,%2,%3}, [%4];"
                    : "=r"(bfv[j][0]), "=r"(bfv[j][1]), "=r"(bfv[j][2]), "=r"(bfv[j][3])
                    : "r"(addr));
            }
            #pragma unroll
            for (int i = 0; i < 4; ++i)
                #pragma unroll
                for (int j = 0; j < 4; ++j) {
                    uint32_t b0 = bfv[j >> 1][(j & 1)];
                    uint32_t b1 = bfv[j >> 1][(j & 1) + 2];
                    asm volatile(
                        "mma.sync.aligned.m16n8k16.row.col.f32.bf16.bf16.f32 "
                        "{%0,%1,%2,%3}, {%4,%5,%6,%7}, {%8,%9}, {%0,%1,%2,%3};"
                        : "+f"(acc[i][j][0]), "+f"(acc[i][j][1]),
                          "+f"(acc[i][j][2]), "+f"(acc[i][j][3])
                        : "r"(af[i][0]), "r"(af[i][1]), "r"(af[i][2]), "r"(af[i][3]),
                          "r"(b0), "r"(b1));
                }
        }
        __syncthreads();
        if (kc + 2 < 4) issue(kc + 2, st);
    }

    // ================= fused epilogue: per-channel block argmax ==============
    float* sval = (float*)smraw;                 // [128][17]
    int*   sidx = (int*)(sval + 128 * 17);       // [128][17]
    float* sbm  = (float*)(sidx + 128 * 17);     // [128]
    int*   sbi  = (int*)(sbm + 128);             // [128]
    int*   scnt = (int*)(sbi + 128);             // [128]
    float* scv  = (float*)(scnt + 128);          // [128][MAXC]
    int*   scp  = (int*)(scv + 128 * MAXC);      // [128][MAXC]
    __shared__ int sLast;

    const int q2 = (lane & 3) * 2;
    const int rowgrp = wm * 8 + gq;
    const int pbase  = mt * 128 + wm * 64;

    #pragma unroll
    for (int j = 0; j < 4; ++j)
        #pragma unroll
        for (int e = 0; e < 2; ++e) {
            int ch = wn * 32 + j * 8 + q2 + e;
            float m = -FLT_MAX; int mi = 0;
            #pragma unroll
            for (int i = 0; i < 4; ++i) {
                int p0 = pbase + i * 16 + gq;
                float v0 = acc[i][j][e];
                float v1 = acc[i][j][e + 2];
                if (v0 > m) { m = v0; mi = p0; }
                if (v1 > m) { m = v1; mi = p0 + 8; }
            }
            sval[ch * 17 + rowgrp] = m;
            sidx[ch * 17 + rowgrp] = mi;
        }
    __syncthreads();

    if (tid < 128) {
        float bv = -FLT_MAX; int bi = 0;
        #pragma unroll
        for (int r = 0; r < 16; ++r) {
            float v  = sval[tid * 17 + r];
            int   ii = sidx[tid * 17 + r];
            if (v > bv || (v == bv && ii < bi)) { bv = v; bi = ii; }
        }
        sbm[tid]  = bv;
        sbi[tid]  = bi;
        scnt[tid] = 1;
        scv[tid * MAXC] = bv;
        scp[tid * MAXC] = bi;
    }
    __syncthreads();

    #pragma unroll
    for (int j = 0; j < 4; ++j)
        #pragma unroll
        for (int e = 0; e < 2; ++e) {
            int ch = wn * 32 + j * 8 + q2 + e;
            float thr = sbm[ch] - MARGIN;
            int   bi  = sbi[ch];
            #pragma unroll
            for (int i = 0; i < 4; ++i) {
                int p0 = pbase + i * 16 + gq;
                float v0 = acc[i][j][e];
                float v1 = acc[i][j][e + 2];
                if (v0 > thr && p0 != bi) {
                    int slot = atomicAdd(&scnt[ch], 1);
                    if (slot < MAXC) { scv[ch * MAXC + slot] = v0; scp[ch * MAXC + slot] = p0; }
                }
                if (v1 > thr && (p0 + 8) != bi) {
                    int slot = atomicAdd(&scnt[ch], 1);
                    if (slot < MAXC) { scv[ch * MAXC + slot] = v1; scp[ch * MAXC + slot] = p0 + 8; }
                }
            }
        }
    __syncthreads();

    if (tid < 128) {
        int o = (b * NMT + mt) * NC + nt * 128 + tid;
        int n = min(scnt[tid], MAXC);
        g_smax[o] = sbm[tid];
        g_scnt[o] = n;
        for (int i = 0; i < n; ++i) {
            g_cval[(size_t)o * MAXC + i] = scv[tid * MAXC + i];
            g_cpos[(size_t)o * MAXC + i] = scp[tid * MAXC + i];
        }
    }

    // =============== last-block merge + scatter for this (b, nt) =============
    __threadfence();          // make this block's summary writes device-visible
    __syncthreads();
    if (tid == 0) {
        int v = atomicAdd(&g_sync[b * 4 + nt], 1);
        sLast = (v == NMT - 1);
        if (sLast) g_sync[b * 4 + nt] = 0;     // replay-safe reset
    }
    __syncthreads();
    if (!sLast) return;
    __threadfence();          // acquire: all 32 blocks' summaries now visible

    // 8 warps x 16 channels each; lane l owns m-tile l (summaries L2-hot)
    for (int cc = 0; cc < 16; ++cc) {
        const int c = nt * 128 + warp * 16 + cc;
        const int o = (b * NMT + lane) * NC + c;
        float tmax = g_smax[o];
        int   cnt  = g_scnt[o];

        float gmax = tmax;
        #pragma unroll
        for (int off = 16; off > 0; off >>= 1)
            gmax = fmaxf(gmax, __shfl_xor_sync(0xffffffffu, gmax, off));
        const float thr = gmax - MARGIN;

        float cvs[MAXC]; int cps[MAXC]; unsigned masks[MAXC]; int total = 0;
        #pragma unroll
        for (int i = 0; i < MAXC; ++i) {
            bool act = (i < cnt);
            cvs[i] = act ? g_cval[(size_t)o * MAXC + i] : -FLT_MAX;
            cps[i] = act ? g_cpos[(size_t)o * MAXC + i] : 0;
            masks[i] = __ballot_sync(0xffffffffu, act && cvs[i] > thr);
            total += __popc(masks[i]);
        }

        const float* kr = kern + (size_t)c * ND;
        float4 k4a = *(const float4*)&kr[lane * 8];
        float4 k4b = *(const float4*)&kr[lane * 8 + 4];

        int bestp;
        if (total == 1 && gmax > MARGIN) {
            bestp = 0;
            #pragma unroll
            for (int i = 0; i < MAXC; ++i)
                if (masks[i]) {
                    int l = __ffs(masks[i]) - 1;
                    bestp = __shfl_sync(0xffffffffu, cps[i], l);
                }
        } else {
            float bestv = -FLT_MAX; bestp = 0x7fffffff; bool have = false;
            #pragma unroll
            for (int i = 0; i < MAXC; ++i) {
                unsigned mask = masks[i];
                while (mask) {
                    int l = __ffs(mask) - 1; mask &= mask - 1;
                    int p = __shfl_sync(0xffffffffu, cps[i], l);
                    const float* xr = x + ((size_t)b * NP + p) * ND + lane * 8;
                    float4 xa = *(const float4*)xr;
                    float4 xb = *(const float4*)(xr + 4);
                    float sum = xa.x * k4a.x + xa.y * k4a.y + xa.z * k4a.z + xa.w * k4a.w
                              + xb.x * k4b.x + xb.y * k4b.y + xb.z * k4b.z + xb.w * k4b.w;
                    #pragma unroll
                    for (int off = 16; off > 0; off >>= 1)
                        sum += __shfl_xor_sync(0xffffffffu, sum, off);
                    if (!have || sum > bestv || (sum == bestv && p < bestp)) {
                        bestv = sum; bestp = p; have = true;
                    }
                }
            }
            if (bestv <= 0.f) bestp = 0;   // all-ReLU-zero => argmax = 0
        }

        float* dst = outf + ((size_t)b * NP + bestp) * ND + lane * 8;
        atomicAdd(&dst[0], k4a.x); atomicAdd(&dst[1], k4a.y);
        atomicAdd(&dst[2], k4a.z); atomicAdd(&dst[3], k4a.w);
        atomicAdd(&dst[4], k4b.x); atomicAdd(&dst[5], k4b.y);
        atomicAdd(&dst[6], k4b.z); atomicAdd(&dst[7], k4b.w);
    }
}

// ---------------------------------------------------------------------------
extern "C" void kernel_launch(void* const* d_in, const int* in_sizes, int n_in,
                              void* d_out, int out_size) {
    const float* x    = (const float*)d_in[0];
    const float* kern = (const float*)d_in[1];
    float*       out  = (float*)d_out;

    prep_kernel<<<128, 256>>>(kern);                      // kernels only

    size_t smem = 2 * 128 * LDA * 4 + 2 * 128 * LDT * 2;  // 110,592 B
    cudaFuncSetAttribute(gemm_kernel,
                         cudaFuncAttributeMaxDynamicSharedMemorySize, (int)smem);
    gemm_kernel<<<dim3(4, NMT, BSZ), 256, smem>>>(x, kern, out);
}

// round 15
// speedup vs baseline: 1.7416x; 1.7416x over previous
#include <cuda_runtime.h>
#include <cuda_bf16.h>
#include <float.h>
#include <stdint.h>

#define BSZ 16
#define NP  4096
#define ND  256
#define NC  512
#define MARGIN 1e-3f

#define NMT  32                 // m-tiles per batch == warp size (by design)
#define MAXC 4
#define LDT  72                 // B smem pitch in bf16 elems (64 + 8 pad)
#define LDA  72                 // A smem pitch in fp32 elems (64 + 8 pad)

// ---- scratch (static device memory) ----
// Summaries stored TRANSPOSED: [b][c][mt] so merge lane-loads coalesce.
__device__ __nv_bfloat16 g_kbf[NC * ND];                  // 256 KB
__device__ float g_smax[BSZ * NC * NMT];
__device__ int   g_scnt[BSZ * NC * NMT];
__device__ float g_cval[(size_t)BSZ * NC * NMT * MAXC];
__device__ int   g_cpos[(size_t)BSZ * NC * NMT * MAXC];

// ---------------------------------------------------------------------------
// Micro-prep: kernels fp32 -> bf16 only (x stays fp32; converted in-gemm).
// ---------------------------------------------------------------------------
__global__ void prep_kernel(const float* __restrict__ kern) {
    int i = blockIdx.x * blockDim.x + threadIdx.x;   // 32768 float4
    float4 v = ((const float4*)kern)[i];
    ((__nv_bfloat162*)g_kbf)[i * 2]     = __floats2bfloat162_rn(v.x, v.y);
    ((__nv_bfloat162*)g_kbf)[i * 2 + 1] = __floats2bfloat162_rn(v.z, v.w);
}

__device__ __forceinline__ uint32_t packbf(float lo, float hi) {
    __nv_bfloat162 h = __floats2bfloat162_rn(lo, hi);
    return *(uint32_t*)&h;
}

// ---------------------------------------------------------------------------
// bf16 tensor GEMM 128x128 tile; A staged fp32 via cp.async and converted to
// bf16 fragments at LDS time. B bf16 via ldmatrix. Fused per-channel argmax
// epilogue + embedded output zeroing. (Round-13 known-good core; only the
// summary-write indexing changed to the transposed layout.)
// ---------------------------------------------------------------------------
__global__ __launch_bounds__(256)
void gemm_kernel(const float* __restrict__ x, float4* __restrict__ out) {
    extern __shared__ char smraw[];
    float*         Asf = (float*)smraw;                       // [2][128*LDA] fp32
    __nv_bfloat16* Bs  = (__nv_bfloat16*)(smraw + 2 * 128 * LDA * 4); // [2][128*LDT]

    const int b = blockIdx.z, mt = blockIdx.y, nt = blockIdx.x;
    const int tid = threadIdx.x, lane = tid & 31, warp = tid >> 5;
    const int wm = warp & 1, wn = warp >> 1;

    const float*         Ag = x + ((size_t)b * NP + mt * 128) * ND;
    const __nv_bfloat16* Bg = g_kbf + (size_t)nt * 128 * ND;

    float acc[4][4][4];
    #pragma unroll
    for (int i = 0; i < 4; ++i)
        #pragma unroll
        for (int j = 0; j < 4; ++j)
            #pragma unroll
            for (int q = 0; q < 4; ++q) acc[i][j][q] = 0.f;

    auto issue = [&](int kc, int st) {
        // A: 128 rows x 64 fp32 = 2048 x 16B
        #pragma unroll
        for (int it = 0; it < 8; ++it) {
            int i = it * 256 + tid;
            int r = i >> 4, c = (i & 15) * 4;
            uint32_t sa = (uint32_t)__cvta_generic_to_shared(
                &Asf[st * 128 * LDA + r * LDA + c]);
            const float* ga = Ag + (size_t)r * ND + kc * 64 + c;
            asm volatile("cp.async.cg.shared.global [%0], [%1], 16;" :: "r"(sa), "l"(ga) : "memory");
        }
        // B: 128 rows x 64 bf16 = 1024 x 16B
        #pragma unroll
        for (int it = 0; it < 4; ++it) {
            int i = it * 256 + tid;
            int r = i >> 3, c = (i & 7) * 8;
            uint32_t sb = (uint32_t)__cvta_generic_to_shared(
                &Bs[st * 128 * LDT + r * LDT + c]);
            const __nv_bfloat16* gb = Bg + (size_t)r * ND + kc * 64 + c;
            asm volatile("cp.async.cg.shared.global [%0], [%1], 16;" :: "r"(sb), "l"(gb) : "memory");
        }
        asm volatile("cp.async.commit_group;" ::: "memory");
    };

    issue(0, 0);
    issue(1, 1);

    // ---- embedded zeroing: this block's 1/2048 slice of out (2048 float4) ----
    {
        const int bid = (b * NMT + mt) * 4 + nt;
        float4* oz = out + (size_t)bid * 2048;
        const float4 z = make_float4(0.f, 0.f, 0.f, 0.f);
        #pragma unroll
        for (int it = 0; it < 8; ++it)
            oz[it * 256 + tid] = z;
    }

    const int lm = lane & 15, lk = (lane >> 4) * 8;   // B ldmatrix addressing
    const int gq = lane >> 2, k2 = (lane & 3) * 2;    // A fragment addressing

    #pragma unroll
    for (int kc = 0; kc < 4; ++kc) {
        if (kc < 3) asm volatile("cp.async.wait_group 1;" ::: "memory");
        else        asm volatile("cp.async.wait_group 0;" ::: "memory");
        __syncthreads();

        int st = kc & 1;
        const float*         Ab = Asf + st * 128 * LDA + (wm * 64) * LDA;
        const __nv_bfloat16* Bb = Bs  + st * 128 * LDT + (wn * 32) * LDT;

        #pragma unroll
        for (int ks = 0; ks < 4; ++ks) {
            const int kb = ks * 16 + k2;
            uint32_t af[4][4], bfv[2][4];
            // A fragments: LDS.64 fp32 pairs + cvt->bf16x2 (conflict-free, pitch 72)
            #pragma unroll
            for (int i = 0; i < 4; ++i) {
                const float* ra = Ab + (i * 16 + gq) * LDA;
                float2 p0 = *(const float2*)(ra + kb);
                float2 p1 = *(const float2*)(ra + 8 * LDA + kb);
                float2 p2 = *(const float2*)(ra + kb + 8);
                float2 p3 = *(const float2*)(ra + 8 * LDA + kb + 8);
                af[i][0] = packbf(p0.x, p0.y);
                af[i][1] = packbf(p1.x, p1.y);
                af[i][2] = packbf(p2.x, p2.y);
                af[i][3] = packbf(p3.x, p3.y);
            }
            #pragma unroll
            for (int j = 0; j < 2; ++j) {
                uint32_t addr = (uint32_t)__cvta_generic_to_shared(
                    Bb + (j * 16 + lm) * LDT + ks * 16 + lk);
                asm volatile("ldmatrix.sync.aligned.m8n8.x4.shared.b16 {%0,%1,%2,%3}, [%4];"
                    : "=r"(bfv[j][0]), "=r"(bfv[j][1]), "=r"(bfv[j][2]), "=r"(bfv[j][3])
                    : "r"(addr));
            }
            #pragma unroll
            for (int i = 0; i < 4; ++i)
                #pragma unroll
                for (int j = 0; j < 4; ++j) {
                    uint32_t b0 = bfv[j >> 1][(j & 1)];
                    uint32_t b1 = bfv[j >> 1][(j & 1) + 2];
                    asm volatile(
                        "mma.sync.aligned.m16n8k16.row.col.f32.bf16.bf16.f32 "
                        "{%0,%1,%2,%3}, {%4,%5,%6,%7}, {%8,%9}, {%0,%1,%2,%3};"
                        : "+f"(acc[i][j][0]), "+f"(acc[i][j][1]),
                          "+f"(acc[i][j][2]), "+f"(acc[i][j][3])
                        : "r"(af[i][0]), "r"(af[i][1]), "r"(af[i][2]), "r"(af[i][3]),
                          "r"(b0), "r"(b1));
                }
        }
        __syncthreads();
        if (kc + 2 < 4) issue(kc + 2, st);
    }

    // ================= fused epilogue: per-channel block argmax ==============
    float* sval = (float*)smraw;                 // [128][17]
    int*   sidx = (int*)(sval + 128 * 17);       // [128][17]
    float* sbm  = (float*)(sidx + 128 * 17);     // [128]
    int*   sbi  = (int*)(sbm + 128);             // [128]
    int*   scnt = (int*)(sbi + 128);             // [128]
    float* scv  = (float*)(scnt + 128);          // [128][MAXC]
    int*   scp  = (int*)(scv + 128 * MAXC);      // [128][MAXC]

    const int q2 = (lane & 3) * 2;
    const int rowgrp = wm * 8 + gq;
    const int pbase  = mt * 128 + wm * 64;

    #pragma unroll
    for (int j = 0; j < 4; ++j)
        #pragma unroll
        for (int e = 0; e < 2; ++e) {
            int ch = wn * 32 + j * 8 + q2 + e;
            float m = -FLT_MAX; int mi = 0;
            #pragma unroll
            for (int i = 0; i < 4; ++i) {
                int p0 = pbase + i * 16 + gq;
                float v0 = acc[i][j][e];
                float v1 = acc[i][j][e + 2];
                if (v0 > m) { m = v0; mi = p0; }
                if (v1 > m) { m = v1; mi = p0 + 8; }
            }
            sval[ch * 17 + rowgrp] = m;
            sidx[ch * 17 + rowgrp] = mi;
        }
    __syncthreads();

    if (tid < 128) {
        float bv = -FLT_MAX; int bi = 0;
        #pragma unroll
        for (int r = 0; r < 16; ++r) {
            float v  = sval[tid * 17 + r];
            int   ii = sidx[tid * 17 + r];
            if (v > bv || (v == bv && ii < bi)) { bv = v; bi = ii; }
        }
        sbm[tid]  = bv;
        sbi[tid]  = bi;
        scnt[tid] = 1;
        scv[tid * MAXC] = bv;
        scp[tid * MAXC] = bi;
    }
    __syncthreads();

    #pragma unroll
    for (int j = 0; j < 4; ++j)
        #pragma unroll
        for (int e = 0; e < 2; ++e) {
            int ch = wn * 32 + j * 8 + q2 + e;
            float thr = sbm[ch] - MARGIN;
            int   bi  = sbi[ch];
            #pragma unroll
            for (int i = 0; i < 4; ++i) {
                int p0 = pbase + i * 16 + gq;
                float v0 = acc[i][j][e];
                float v1 = acc[i][j][e + 2];
                if (v0 > thr && p0 != bi) {
                    int slot = atomicAdd(&scnt[ch], 1);
                    if (slot < MAXC) { scv[ch * MAXC + slot] = v0; scp[ch * MAXC + slot] = p0; }
                }
                if (v1 > thr && (p0 + 8) != bi) {
                    int slot = atomicAdd(&scnt[ch], 1);
                    if (slot < MAXC) { scv[ch * MAXC + slot] = v1; scp[ch * MAXC + slot] = p0 + 8; }
                }
            }
        }
    __syncthreads();

    // transposed summary write: o = ((b*NC + c) * NMT + mt)
    if (tid < 128) {
        int o = ((b * NC + nt * 128 + tid) * NMT) + mt;
        int n = min(scnt[tid], MAXC);
        g_smax[o] = sbm[tid];
        g_scnt[o] = n;
        for (int i = 0; i < n; ++i) {
            g_cval[(size_t)o * MAXC + i] = scv[tid * MAXC + i];
            g_cpos[(size_t)o * MAXC + i] = scp[tid * MAXC + i];
        }
    }
}

// ---------------------------------------------------------------------------
// Merge + scatter: warp per (b,c); lane l owns m-tile l. Transposed summary
// layout makes every warp load coalesced (128 B / 512 B lines instead of 32
// scattered lines). Fast path: unique margin-survivor skips rescore loads.
// ---------------------------------------------------------------------------
__global__ __launch_bounds__(256)
void merge_scatter_kernel(const float* __restrict__ x,
                          const float* __restrict__ kern,
                          float* __restrict__ out) {
    int task = blockIdx.x * 8 + (threadIdx.x >> 5);
    int lane = threadIdx.x & 31;
    int b = task >> 9, c = task & (NC - 1);

    const int o = (b * NC + c) * NMT + lane;   // coalesced per-warp
    float tmax = g_smax[o];
    int   cnt  = g_scnt[o];

    float gmax = tmax;
    #pragma unroll
    for (int off = 16; off > 0; off >>= 1)
        gmax = fmaxf(gmax, __shfl_xor_sync(0xffffffffu, gmax, off));
    const float thr = gmax - MARGIN;

    float cvs[MAXC]; int cps[MAXC]; unsigned masks[MAXC]; int total = 0;
    #pragma unroll
    for (int i = 0; i < MAXC; ++i) {
        bool act = (i < cnt);
        cvs[i] = act ? g_cval[(size_t)o * MAXC + i] : -FLT_MAX;
        cps[i] = act ? g_cpos[(size_t)o * MAXC + i] : 0;
        masks[i] = __ballot_sync(0xffffffffu, act && cvs[i] > thr);
        total += __popc(masks[i]);
    }

    const float* kr = kern + (size_t)c * ND;
    float4 k4a = *(const float4*)&kr[lane * 8];
    float4 k4b = *(const float4*)&kr[lane * 8 + 4];

    int bestp;
    if (total == 1 && gmax > MARGIN) {
        bestp = 0;
        #pragma unroll
        for (int i = 0; i < MAXC; ++i)
            if (masks[i]) {
                int l = __ffs(masks[i]) - 1;
                bestp = __shfl_sync(0xffffffffu, cps[i], l);
            }
    } else {
        float bestv = -FLT_MAX; bestp = 0x7fffffff; bool have = false;
        #pragma unroll
        for (int i = 0; i < MAXC; ++i) {
            unsigned mask = masks[i];
            while (mask) {
                int l = __ffs(mask) - 1; mask &= mask - 1;
                int p = __shfl_sync(0xffffffffu, cps[i], l);
                const float* xr = x + ((size_t)b * NP + p) * ND + lane * 8;
                float4 xa = *(const float4*)xr;
                float4 xb = *(const float4*)(xr + 4);
                float sum = xa.x * k4a.x + xa.y * k4a.y + xa.z * k4a.z + xa.w * k4a.w
                          + xb.x * k4b.x + xb.y * k4b.y + xb.z * k4b.z + xb.w * k4b.w;
                #pragma unroll
                for (int off = 16; off > 0; off >>= 1)
                    sum += __shfl_xor_sync(0xffffffffu, sum, off);
                if (!have || sum > bestv || (sum == bestv && p < bestp)) {
                    bestv = sum; bestp = p; have = true;
                }
            }
        }
        if (bestv <= 0.f) bestp = 0;   // all-ReLU-zero => argmax = 0
    }

    float* dst = out + ((size_t)b * NP + bestp) * ND + lane * 8;
    atomicAdd(&dst[0], k4a.x); atomicAdd(&dst[1], k4a.y);
    atomicAdd(&dst[2], k4a.z); atomicAdd(&dst[3], k4a.w);
    atomicAdd(&dst[4], k4b.x); atomicAdd(&dst[5], k4b.y);
    atomicAdd(&dst[6], k4b.z); atomicAdd(&dst[7], k4b.w);
}

// ---------------------------------------------------------------------------
extern "C" void kernel_launch(void* const* d_in, const int* in_sizes, int n_in,
                              void* d_out, int out_size) {
    const float* x    = (const float*)d_in[0];
    const float* kern = (const float*)d_in[1];
    float*       out  = (float*)d_out;

    prep_kernel<<<128, 256>>>(kern);                      // kernels only

    size_t smem = 2 * 128 * LDA * 4 + 2 * 128 * LDT * 2;  // 110,592 B
    cudaFuncSetAttribute(gemm_kernel,
                         cudaFuncAttributeMaxDynamicSharedMemorySize, (int)smem);
    gemm_kernel<<<dim3(4, NMT, BSZ), 256, smem>>>(x, (float4*)out);

    merge_scatter_kernel<<<BSZ * NC / 8, 256>>>(x, kern, out);
}

// round 16
// speedup vs baseline: 1.8147x; 1.0420x over previous
#include <cuda_runtime.h>
#include <cuda_bf16.h>
#include <float.h>
#include <stdint.h>

#define BSZ 16
#define NP  4096
#define ND  256
#define NC  512
#define MARGIN 1e-3f

#define NMT  32                 // m-tiles per batch == warp size (by design)
#define MAXC 4
#define LDT  72                 // B smem pitch in bf16 elems (64 + 8 pad)
#define LDA  72                 // A smem pitch in fp32 elems (64 + 8 pad)

// ---- scratch (static device memory); layout [b][mt][c] (gemm-write coalesced)
__device__ __nv_bfloat16 g_kbf[NC * ND];                  // 256 KB
__device__ float g_smax[BSZ * NMT * NC];
__device__ int   g_scnt[BSZ * NMT * NC];
__device__ float g_cval[(size_t)BSZ * NMT * NC * MAXC];
__device__ int   g_cpos[(size_t)BSZ * NMT * NC * MAXC];

// ---------------------------------------------------------------------------
// Micro-prep: kernels fp32 -> bf16 only (x stays fp32; converted in-gemm).
// ---------------------------------------------------------------------------
__global__ void prep_kernel(const float* __restrict__ kern) {
    int i = blockIdx.x * blockDim.x + threadIdx.x;   // 32768 float4
    float4 v = ((const float4*)kern)[i];
    ((__nv_bfloat162*)g_kbf)[i * 2]     = __floats2bfloat162_rn(v.x, v.y);
    ((__nv_bfloat162*)g_kbf)[i * 2 + 1] = __floats2bfloat162_rn(v.z, v.w);
}

__device__ __forceinline__ uint32_t packbf(float lo, float hi) {
    __nv_bfloat162 h = __floats2bfloat162_rn(lo, hi);
    return *(uint32_t*)&h;
}

// ---------------------------------------------------------------------------
// bf16 tensor GEMM 128x128 tile; A staged fp32 via cp.async, converted to
// bf16 fragments at LDS time; B bf16 via ldmatrix. Fused per-channel argmax
// epilogue + embedded output zeroing. (Round-13 known-good, byte-identical.)
// ---------------------------------------------------------------------------
__global__ __launch_bounds__(256)
void gemm_kernel(const float* __restrict__ x, float4* __restrict__ out) {
    extern __shared__ char smraw[];
    float*         Asf = (float*)smraw;                       // [2][128*LDA] fp32
    __nv_bfloat16* Bs  = (__nv_bfloat16*)(smraw + 2 * 128 * LDA * 4); // [2][128*LDT]

    const int b = blockIdx.z, mt = blockIdx.y, nt = blockIdx.x;
    const int tid = threadIdx.x, lane = tid & 31, warp = tid >> 5;
    const int wm = warp & 1, wn = warp >> 1;

    const float*         Ag = x + ((size_t)b * NP + mt * 128) * ND;
    const __nv_bfloat16* Bg = g_kbf + (size_t)nt * 128 * ND;

    float acc[4][4][4];
    #pragma unroll
    for (int i = 0; i < 4; ++i)
        #pragma unroll
        for (int j = 0; j < 4; ++j)
            #pragma unroll
            for (int q = 0; q < 4; ++q) acc[i][j][q] = 0.f;

    auto issue = [&](int kc, int st) {
        #pragma unroll
        for (int it = 0; it < 8; ++it) {              // A: 2048 x 16B fp32
            int i = it * 256 + tid;
            int r = i >> 4, c = (i & 15) * 4;
            uint32_t sa = (uint32_t)__cvta_generic_to_shared(
                &Asf[st * 128 * LDA + r * LDA + c]);
            const float* ga = Ag + (size_t)r * ND + kc * 64 + c;
            asm volatile("cp.async.cg.shared.global [%0], [%1], 16;" :: "r"(sa), "l"(ga) : "memory");
        }
        #pragma unroll
        for (int it = 0; it < 4; ++it) {              // B: 1024 x 16B bf16
            int i = it * 256 + tid;
            int r = i >> 3, c = (i & 7) * 8;
            uint32_t sb = (uint32_t)__cvta_generic_to_shared(
                &Bs[st * 128 * LDT + r * LDT + c]);
            const __nv_bfloat16* gb = Bg + (size_t)r * ND + kc * 64 + c;
            asm volatile("cp.async.cg.shared.global [%0], [%1], 16;" :: "r"(sb), "l"(gb) : "memory");
        }
        asm volatile("cp.async.commit_group;" ::: "memory");
    };

    issue(0, 0);
    issue(1, 1);

    // ---- embedded zeroing: this block's 2048-float4 slice of out ----
    {
        const int bid = (b * NMT + mt) * 4 + nt;
        float4* oz = out + (size_t)bid * 2048;
        const float4 z = make_float4(0.f, 0.f, 0.f, 0.f);
        #pragma unroll
        for (int it = 0; it < 8; ++it)
            oz[it * 256 + tid] = z;
    }

    const int lm = lane & 15, lk = (lane >> 4) * 8;
    const int gq = lane >> 2, k2 = (lane & 3) * 2;

    #pragma unroll
    for (int kc = 0; kc < 4; ++kc) {
        if (kc < 3) asm volatile("cp.async.wait_group 1;" ::: "memory");
        else        asm volatile("cp.async.wait_group 0;" ::: "memory");
        __syncthreads();

        int st = kc & 1;
        const float*         Ab = Asf + st * 128 * LDA + (wm * 64) * LDA;
        const __nv_bfloat16* Bb = Bs  + st * 128 * LDT + (wn * 32) * LDT;

        #pragma unroll
        for (int ks = 0; ks < 4; ++ks) {
            const int kb = ks * 16 + k2;
            uint32_t af[4][4], bfv[2][4];
            #pragma unroll
            for (int i = 0; i < 4; ++i) {
                const float* ra = Ab + (i * 16 + gq) * LDA;
                float2 p0 = *(const float2*)(ra + kb);
                float2 p1 = *(const float2*)(ra + 8 * LDA + kb);
                float2 p2 = *(const float2*)(ra + kb + 8);
                float2 p3 = *(const float2*)(ra + 8 * LDA + kb + 8);
                af[i][0] = packbf(p0.x, p0.y);
                af[i][1] = packbf(p1.x, p1.y);
                af[i][2] = packbf(p2.x, p2.y);
                af[i][3] = packbf(p3.x, p3.y);
            }
            #pragma unroll
            for (int j = 0; j < 2; ++j) {
                uint32_t addr = (uint32_t)__cvta_generic_to_shared(
                    Bb + (j * 16 + lm) * LDT + ks * 16 + lk);
                asm volatile("ldmatrix.sync.aligned.m8n8.x4.shared.b16 {%0,%1,%2,%3}, [%4];"
                    : "=r"(bfv[j][0]), "=r"(bfv[j][1]), "=r"(bfv[j][2]), "=r"(bfv[j][3])
                    : "r"(addr));
            }
            #pragma unroll
            for (int i = 0; i < 4; ++i)
                #pragma unroll
                for (int j = 0; j < 4; ++j) {
                    uint32_t b0 = bfv[j >> 1][(j & 1)];
                    uint32_t b1 = bfv[j >> 1][(j & 1) + 2];
                    asm volatile(
                        "mma.sync.aligned.m16n8k16.row.col.f32.bf16.bf16.f32 "
                        "{%0,%1,%2,%3}, {%4,%5,%6,%7}, {%8,%9}, {%0,%1,%2,%3};"
                        : "+f"(acc[i][j][0]), "+f"(acc[i][j][1]),
                          "+f"(acc[i][j][2]), "+f"(acc[i][j][3])
                        : "r"(af[i][0]), "r"(af[i][1]), "r"(af[i][2]), "r"(af[i][3]),
                          "r"(b0), "r"(b1));
                }
        }
        __syncthreads();
        if (kc + 2 < 4) issue(kc + 2, st);
    }

    // ================= fused epilogue: per-channel block argmax ==============
    float* sval = (float*)smraw;                 // [128][17]
    int*   sidx = (int*)(sval + 128 * 17);       // [128][17]
    float* sbm  = (float*)(sidx + 128 * 17);     // [128]
    int*   sbi  = (int*)(sbm + 128);             // [128]
    int*   scnt = (int*)(sbi + 128);             // [128]
    float* scv  = (float*)(scnt + 128);          // [128][MAXC]
    int*   scp  = (int*)(scv + 128 * MAXC);      // [128][MAXC]

    const int q2 = (lane & 3) * 2;
    const int rowgrp = wm * 8 + gq;
    const int pbase  = mt * 128 + wm * 64;

    #pragma unroll
    for (int j = 0; j < 4; ++j)
        #pragma unroll
        for (int e = 0; e < 2; ++e) {
            int ch = wn * 32 + j * 8 + q2 + e;
            float m = -FLT_MAX; int mi = 0;
            #pragma unroll
            for (int i = 0; i < 4; ++i) {
                int p0 = pbase + i * 16 + gq;
                float v0 = acc[i][j][e];
                float v1 = acc[i][j][e + 2];
                if (v0 > m) { m = v0; mi = p0; }
                if (v1 > m) { m = v1; mi = p0 + 8; }
            }
            sval[ch * 17 + rowgrp] = m;
            sidx[ch * 17 + rowgrp] = mi;
        }
    __syncthreads();

    if (tid < 128) {
        float bv = -FLT_MAX; int bi = 0;
        #pragma unroll
        for (int r = 0; r < 16; ++r) {
            float v  = sval[tid * 17 + r];
            int   ii = sidx[tid * 17 + r];
            if (v > bv || (v == bv && ii < bi)) { bv = v; bi = ii; }
        }
        sbm[tid]  = bv;
        sbi[tid]  = bi;
        scnt[tid] = 1;
        scv[tid * MAXC] = bv;
        scp[tid * MAXC] = bi;
    }
    __syncthreads();

    #pragma unroll
    for (int j = 0; j < 4; ++j)
        #pragma unroll
        for (int e = 0; e < 2; ++e) {
            int ch = wn * 32 + j * 8 + q2 + e;
            float thr = sbm[ch] - MARGIN;
            int   bi  = sbi[ch];
            #pragma unroll
            for (int i = 0; i < 4; ++i) {
                int p0 = pbase + i * 16 + gq;
                float v0 = acc[i][j][e];
                float v1 = acc[i][j][e + 2];
                if (v0 > thr && p0 != bi) {
                    int slot = atomicAdd(&scnt[ch], 1);
                    if (slot < MAXC) { scv[ch * MAXC + slot] = v0; scp[ch * MAXC + slot] = p0; }
                }
                if (v1 > thr && (p0 + 8) != bi) {
                    int slot = atomicAdd(&scnt[ch], 1);
                    if (slot < MAXC) { scv[ch * MAXC + slot] = v1; scp[ch * MAXC + slot] = p0 + 8; }
                }
            }
        }
    __syncthreads();

    if (tid < 128) {
        int o = (b * NMT + mt) * NC + nt * 128 + tid;     // coalesced write
        int n = min(scnt[tid], MAXC);
        g_smax[o] = sbm[tid];
        g_scnt[o] = n;
        for (int i = 0; i < n; ++i) {
            g_cval[(size_t)o * MAXC + i] = scv[tid * MAXC + i];
            g_cpos[(size_t)o * MAXC + i] = scp[tid * MAXC + i];
        }
    }
}

// ---------------------------------------------------------------------------
// Merge + scatter with SMEM-STAGED summaries: block = 8 tasks (same batch,
// 8 consecutive channels). 256 threads cooperatively load all 32 m-tile
// summaries for the 8 channels with coalesced global accesses, then each
// warp (lane = m-tile) runs the fast-path/rescore/scatter from smem.
// ---------------------------------------------------------------------------
__global__ __launch_bounds__(256)
void merge_scatter_kernel(const float* __restrict__ x,
                          const float* __restrict__ kern,
                          float* __restrict__ out) {
    __shared__ float  s_max [32 * 9];     // [mt][cj], pitch 9 (conflict-free)
    __shared__ int    s_cnt [32 * 9];
    __shared__ float4 s_cval[32 * 9];     // 4 candidate values packed
    __shared__ int4   s_cpos[32 * 9];

    const int tidx = threadIdx.x;
    const int warp = tidx >> 5, lane = tidx & 31;
    const int task0 = blockIdx.x * 8;
    const int b = task0 >> 9, c0 = task0 & (NC - 1);

    // cooperative stage: thread t -> (mt = t>>3, cj = t&7); coalesced loads
    {
        int mt = tidx >> 3, cj = tidx & 7;
        int o = (b * NMT + mt) * NC + c0 + cj;
        s_max [mt * 9 + cj] = g_smax[o];
        s_cnt [mt * 9 + cj] = g_scnt[o];
        s_cval[mt * 9 + cj] = *(const float4*)&g_cval[(size_t)o * MAXC];
        s_cpos[mt * 9 + cj] = *(const int4*)&g_cpos[(size_t)o * MAXC];
    }
    __syncthreads();

    const int c = c0 + warp;
    const int si = lane * 9 + warp;       // lane's m-tile slot for this task
    float tmax = s_max[si];
    int   cnt  = s_cnt[si];
    float4 cv4 = s_cval[si];
    int4   cp4 = s_cpos[si];

    float gmax = tmax;
    #pragma unroll
    for (int off = 16; off > 0; off >>= 1)
        gmax = fmaxf(gmax, __shfl_xor_sync(0xffffffffu, gmax, off));
    const float thr = gmax - MARGIN;

    float cvs[MAXC] = { cv4.x, cv4.y, cv4.z, cv4.w };
    int   cps[MAXC] = { cp4.x, cp4.y, cp4.z, cp4.w };
    unsigned masks[MAXC]; int total = 0;
    #pragma unroll
    for (int i = 0; i < MAXC; ++i) {
        bool act = (i < cnt);
        if (!act) { cvs[i] = -FLT_MAX; cps[i] = 0; }
        masks[i] = __ballot_sync(0xffffffffu, act && cvs[i] > thr);
        total += __popc(masks[i]);
    }

    const float* kr = kern + (size_t)c * ND;
    float4 k4a = *(const float4*)&kr[lane * 8];
    float4 k4b = *(const float4*)&kr[lane * 8 + 4];

    int bestp;
    if (total == 1 && gmax > MARGIN) {
        bestp = 0;
        #pragma unroll
        for (int i = 0; i < MAXC; ++i)
            if (masks[i]) {
                int l = __ffs(masks[i]) - 1;
                bestp = __shfl_sync(0xffffffffu, cps[i], l);
            }
    } else {
        float bestv = -FLT_MAX; bestp = 0x7fffffff; bool have = false;
        #pragma unroll
        for (int i = 0; i < MAXC; ++i) {
            unsigned mask = masks[i];
            while (mask) {
                int l = __ffs(mask) - 1; mask &= mask - 1;
                int p = __shfl_sync(0xffffffffu, cps[i], l);
                const float* xr = x + ((size_t)b * NP + p) * ND + lane * 8;
                float4 xa = *(const float4*)xr;
                float4 xb = *(const float4*)(xr + 4);
                float sum = xa.x * k4a.x + xa.y * k4a.y + xa.z * k4a.z + xa.w * k4a.w
                          + xb.x * k4b.x + xb.y * k4b.y + xb.z * k4b.z + xb.w * k4b.w;
                #pragma unroll
                for (int off = 16; off > 0; off >>= 1)
                    sum += __shfl_xor_sync(0xffffffffu, sum, off);
                if (!have || sum > bestv || (sum == bestv && p < bestp)) {
                    bestv = sum; bestp = p; have = true;
                }
            }
        }
        if (bestv <= 0.f) bestp = 0;   // all-ReLU-zero => argmax = 0
    }

    float* dst = out + ((size_t)b * NP + bestp) * ND + lane * 8;
    atomicAdd(&dst[0], k4a.x); atomicAdd(&dst[1], k4a.y);
    atomicAdd(&dst[2], k4a.z); atomicAdd(&dst[3], k4a.w);
    atomicAdd(&dst[4], k4b.x); atomicAdd(&dst[5], k4b.y);
    atomicAdd(&dst[6], k4b.z); atomicAdd(&dst[7], k4b.w);
}

// ---------------------------------------------------------------------------
extern "C" void kernel_launch(void* const* d_in, const int* in_sizes, int n_in,
                              void* d_out, int out_size) {
    const float* x    = (const float*)d_in[0];
    const float* kern = (const float*)d_in[1];
    float*       out  = (float*)d_out;

    prep_kernel<<<128, 256>>>(kern);                      // kernels only

    size_t smem = 2 * 128 * LDA * 4 + 2 * 128 * LDT * 2;  // 110,592 B
    cudaFuncSetAttribute(gemm_kernel,
                         cudaFuncAttributeMaxDynamicSharedMemorySize, (int)smem);
    gemm_kernel<<<dim3(4, NMT, BSZ), 256, smem>>>(x, (float4*)out);

    merge_scatter_kernel<<<BSZ * NC / 8, 256>>>(x, kern, out);
}